// round 16
// baseline (speedup 1.0000x reference)
#include <cuda_runtime.h>
#include <cuda_fp16.h>
#include <cstdint>

// Problem constants
#define B_SZ   16
#define CIN    128
#define COUT   128
#define HD     512
#define HW     128      // input H = W
#define OHW    126      // output H = W (VALID conv, K=3)
#define REM    1152     // CIN * 9
#define WSIZE  147456   // COUT * REM

// Single dynamic-smem symbol for the whole TU
extern __shared__ __align__(16) char dsm[];

// ---------------------------------------------------------------------------
// Device-global scratch (no allocation allowed anywhere)
// ---------------------------------------------------------------------------
// conv weights fp16, layout [b][co][k], k = tap*128 + ci (tap-major)
__device__ __align__(16) __half g_wh[B_SZ * WSIZE];
// x transposed to [b][ih][iw][ci] fp16 (+pad: conv may read past end)
__device__ __align__(16) __half g_xh[B_SZ * HW * HW * CIN + 1024];
__device__ float g_bias[B_SZ * COUT];

// ---------------------------------------------------------------------------
// helpers
// ---------------------------------------------------------------------------
__device__ __forceinline__ uint32_t smem_to_u32(const void* p) {
    uint32_t a;
    asm("{ .reg .u64 t; cvta.to.shared.u64 t, %1; cvt.u32.u64 %0, t; }"
        : "=r"(a) : "l"(p));
    return a;
}
__device__ __forceinline__ void cp16(void* dst, const void* src) {
    uint32_t d = smem_to_u32(dst);
    asm volatile("cp.async.cg.shared.global [%0], [%1], 16;"
                 :: "r"(d), "l"(src) : "memory");
}
#define CP_COMMIT()  asm volatile("cp.async.commit_group;" ::: "memory")
#define CP_WAIT(n)   asm volatile("cp.async.wait_group %0;" :: "n"(n) : "memory")

// mma.sync m16n8k16 row.col fp16 -> f32 accumulate
__device__ __forceinline__ void mma16816(float* c, const uint32_t* a,
                                         const uint32_t* b) {
    asm volatile(
        "mma.sync.aligned.m16n8k16.row.col.f32.f16.f16.f32 "
        "{%0,%1,%2,%3}, {%4,%5,%6,%7}, {%8,%9}, {%0,%1,%2,%3};"
        : "+f"(c[0]), "+f"(c[1]), "+f"(c[2]), "+f"(c[3])
        : "r"(a[0]), "r"(a[1]), "r"(a[2]), "r"(a[3]), "r"(b[0]), "r"(b[1]));
}
// ldmatrix (sm_75+, legal on plain sm_103 target)
__device__ __forceinline__ void ldsm_x4(uint32_t* r, uint32_t addr) {
    asm volatile("ldmatrix.sync.aligned.m8n8.x4.shared.b16 {%0,%1,%2,%3}, [%4];"
                 : "=r"(r[0]), "=r"(r[1]), "=r"(r[2]), "=r"(r[3]) : "r"(addr));
}
__device__ __forceinline__ void ldsm_x2(uint32_t* r, uint32_t addr) {
    asm volatile("ldmatrix.sync.aligned.m8n8.x2.shared.b16 {%0,%1}, [%2];"
                 : "=r"(r[0]), "=r"(r[1]) : "r"(addr));
}

// f32x2 helpers (hyper GEMM keeps the exact-fp32 FFMA2 path)
__device__ __forceinline__ void fma2(unsigned long long& d,
                                     unsigned long long a, unsigned long long b) {
    asm("fma.rn.f32x2 %0, %1, %2, %0;" : "+l"(d) : "l"(a), "l"(b));
}
__device__ __forceinline__ unsigned long long dup2(float v) {
    unsigned long long r; unsigned u = __float_as_uint(v);
    asm("mov.b64 %0, {%1, %1};" : "=l"(r) : "r"(u));
    return r;
}
__device__ __forceinline__ void unpack2(unsigned long long v, float& lo, float& hi) {
    asm("mov.b64 {%0, %1}, %2;" : "=f"(lo), "=f"(hi) : "l"(v));
}

// ---------------------------------------------------------------------------
// Kernel 1: hyper GEMM, register-streaming Wh.
// Each thread owns 2 consecutive n-rows of Wh and streams them as float4;
// h is staged once in smem as f32x2 b-pairs [k][8], read via LDS.64 broadcast.
// 288 blocks x 256 threads x 2 n = 147456. Exact fp32 math (unchanged error).
// ---------------------------------------------------------------------------
__global__ __launch_bounds__(256, 2)
void hyper_gemm_kernel(const float* __restrict__ Wh,
                       const float* __restrict__ h,
                       const float* __restrict__ bh) {
    unsigned long long* hs = reinterpret_cast<unsigned long long*>(dsm); // [512][8]
    const int t = threadIdx.x;

    for (int i = t; i < HD * 8; i += 256) {
        int k = i >> 3, p = i & 7;
        unsigned long long v;
        asm("mov.b64 %0, {%1, %2};" : "=l"(v)
            : "r"(__float_as_uint(h[(2 * p) * HD + k])),
              "r"(__float_as_uint(h[(2 * p + 1) * HD + k])));
        hs[i] = v;
    }
    __syncthreads();

    const int n0 = blockIdx.x * 512 + t * 2;
    const float4* w0 = reinterpret_cast<const float4*>(Wh) + (size_t)n0 * (HD / 4);
    const float4* w1 = w0 + (HD / 4);

    unsigned long long acc[2][8];
#pragma unroll
    for (int j = 0; j < 2; j++)
#pragma unroll
        for (int p = 0; p < 8; p++) acc[j][p] = 0ULL;

#pragma unroll 2
    for (int kq = 0; kq < HD / 4; kq++) {
        float4 a = w0[kq];
        float4 c = w1[kq];
        const unsigned long long* hp = hs + kq * 32;
        float av[4] = {a.x, a.y, a.z, a.w};
        float cv[4] = {c.x, c.y, c.z, c.w};
#pragma unroll
        for (int kk = 0; kk < 4; kk++) {
            unsigned long long da = dup2(av[kk]);
            unsigned long long dc = dup2(cv[kk]);
#pragma unroll
            for (int p = 0; p < 8; p++) {
                unsigned long long hv = hp[kk * 8 + p];   // LDS.64 broadcast
                fma2(acc[0][p], hv, da);
                fma2(acc[1][p], hv, dc);
            }
        }
    }

    // Epilogue: add bh, fp16 round, scatter into tap-major [b][co][k]
#pragma unroll
    for (int j = 0; j < 2; j++) {
        int n   = n0 + j;
        float bv = bh[n];
        int co  = n / REM;
        int rem = n - co * REM;
        int ci  = rem / 9;
        int tap = rem - ci * 9;
        int k   = tap * 128 + ci;
#pragma unroll
        for (int p = 0; p < 8; p++) {
            float lo, hi;
            unpack2(acc[j][p], lo, hi);
            g_wh[((size_t)((2 * p)     * COUT + co)) * REM + k] =
                __float2half_rn(lo + bv);
            g_wh[((size_t)((2 * p + 1) * COUT + co)) * REM + k] =
                __float2half_rn(hi + bv);
        }
    }
}

// ---------------------------------------------------------------------------
// Kernel 2: x transpose NCHW -> [b][ih][iw][ci], fp16
// ---------------------------------------------------------------------------
__global__ __launch_bounds__(256)
void xpose_kernel(const float* __restrict__ x) {
    __shared__ float ts[32][33];
    const int ih = blockIdx.x, b = blockIdx.y;
    const int t = threadIdx.x, j = t & 31, g = t >> 5;

    for (int cit = 0; cit < 4; cit++)
        for (int iwt = 0; iwt < 4; iwt++) {
            __syncthreads();
#pragma unroll
            for (int ii = 0; ii < 4; ii++) {
                int ci = cit * 32 + g + ii * 8;
                ts[g + ii * 8][j] =
                    x[(((size_t)b * CIN + ci) * HW + ih) * HW + iwt * 32 + j];
            }
            __syncthreads();
#pragma unroll
            for (int ii = 0; ii < 4; ii++) {
                int iwl = g + ii * 8;
                size_t dst = (((size_t)b * HW + ih) * HW + iwt * 32 + iwl) * CIN
                             + cit * 32 + j;
                g_xh[dst] = __float2half_rn(ts[j][iwl]);
            }
        }
}

// ---------------------------------------------------------------------------
// Kernel 3: per-sample bias (unchanged)
// ---------------------------------------------------------------------------
__global__ void hyper_bias_kernel(const float* __restrict__ h,
                                  const float* __restrict__ Wb,
                                  const float* __restrict__ bb) {
    int out  = blockIdx.x * 8 + (threadIdx.x >> 5);
    int lane = threadIdx.x & 31;
    int b  = out >> 7;
    int co = out & 127;
    float s = 0.f;
    for (int k = lane; k < HD; k += 32)
        s += h[b * HD + k] * Wb[co * HD + k];
#pragma unroll
    for (int o = 16; o > 0; o >>= 1) s += __shfl_xor_sync(0xffffffffu, s, o);
    if (lane == 0) g_bias[out] = s + bb[co];
}

// ---------------------------------------------------------------------------
// Kernel 4: HMMA conv, single-pass fp16, fragments via ldmatrix.
// CTA = (oh, b): M=128 co x N=128 ow, K=1152 tap-major. 256 thr, 8 warps,
// warp tile 64x32. 18 chunks of KC=64, cp.async double buffer, 2 CTAs/SM.
// Per ks-iter: 4x ldmatrix.x4 (A) + 4x ldmatrix.x2 (B) replace 24 LDS.32.
// ---------------------------------------------------------------------------
#define NCH   18
#define AROW  72                 // fp16 elems per smem row (64 data + 8 pad)
#define MATE  (128 * AROW)       // elems per matrix  (9216)
#define STGE  (2 * MATE)         // elems per stage   (A|B)
#define CONV_SMEM (2 * STGE * 2) // bytes = 73728

__global__ __launch_bounds__(256, 2)
void conv_mma_kernel(float* __restrict__ y) {
    __half* sm = reinterpret_cast<__half*>(dsm);
    const int t    = threadIdx.x;
    const int lane = t & 31, wid = t >> 5;
    const int g    = lane >> 2, tq = lane & 3;
    const int wrow = wid >> 2, wcol = wid & 3;   // 2x4 warp grid
    const int oh   = blockIdx.x;        // 0..125
    const int b    = blockIdx.y;        // 0..15

    const __half* whp = g_wh + (size_t)b * WSIZE;

    // ldmatrix per-lane byte offsets within a stage.
    // A (x4): lanes 0-7 rows r..r+7 @k0 | 8-15 rows+8 @k0 | 16-23 rows @k0+8
    //         | 24-31 rows+8 @k0+8  -> frags a0,a1,a2,a3 in mma order.
    // B (x2): lanes 0-7 rows n..n+7 @k0 | 8-15 same rows @k0+8 -> b0,b1.
    const uint32_t smb  = smem_to_u32(sm);
    const uint32_t aoff = ((wrow * 64 + (lane & 15)) * AROW
                           + ((lane >> 4) << 3)) * 2;
    const uint32_t boff = ((uint32_t)MATE + (wcol * 32 + (lane & 7)) * AROW
                           + (((lane >> 3) & 1) << 3)) * 2;

    float acc[4][4][4];
#pragma unroll
    for (int mi = 0; mi < 4; mi++)
#pragma unroll
        for (int ni = 0; ni < 4; ni++)
#pragma unroll
            for (int q = 0; q < 4; q++) acc[mi][ni][q] = 0.f;

    auto load_stage = [&](int s, int kc) {
        const int tap = kc >> 1, ci0 = (kc & 1) * 64;
        const int kh = tap / 3, kw = tap - 3 * kh;
        __half* st = sm + s * STGE;
        const size_t xoff = (((size_t)(b * HW) + oh + kh) * HW + kw) * CIN + ci0;
        const __half* xh = g_xh + xoff;
#pragma unroll
        for (int i = 0; i < 4; i++) {
            int idx = t + i * 256;
            int row = idx >> 3, c = idx & 7;    // row: co or px; c: 16B column
            int so = row * AROW + c * 8;
            cp16(st + so,        whp + row * REM + kc * 64 + c * 8);
            cp16(st + MATE + so, xh + (size_t)row * CIN + c * 8);
        }
        CP_COMMIT();
    };

    load_stage(0, 0);

    for (int kc = 0; kc < NCH; kc++) {
        if (kc + 1 < NCH) { load_stage((kc + 1) & 1, kc + 1); CP_WAIT(1); }
        else              { CP_WAIT(0); }
        __syncthreads();

        const uint32_t sb = smb + (kc & 1) * (STGE * 2);

#pragma unroll
        for (int ks = 0; ks < 4; ks++) {
            uint32_t ahf[4][4], bf[4][2];
            const uint32_t ab = sb + aoff + ks * 32;
            const uint32_t bb2 = sb + boff + ks * 32;
#pragma unroll
            for (int mi = 0; mi < 4; mi++)
                ldsm_x4(ahf[mi], ab + mi * (16 * AROW * 2));
#pragma unroll
            for (int ni = 0; ni < 4; ni++)
                ldsm_x2(bf[ni], bb2 + ni * (8 * AROW * 2));
#pragma unroll
            for (int mi = 0; mi < 4; mi++)
#pragma unroll
                for (int ni = 0; ni < 4; ni++)
                    mma16816(acc[mi][ni], ahf[mi], bf[ni]);
        }
        __syncthreads();
    }

    // Epilogue: + per-sample bias, guarded stores (ow < 126)
    const float* bp = g_bias + b * COUT;
#pragma unroll
    for (int mi = 0; mi < 4; mi++) {
        int co0 = wrow * 64 + mi * 16 + g;       // c0/c1 rows; c2/c3 at co0+8
        float bias0 = bp[co0], bias1 = bp[co0 + 8];
        float* y0 = y + (((size_t)(b * COUT) + co0) * OHW + oh) * OHW;
        float* y1 = y0 + (size_t)8 * OHW * OHW;
#pragma unroll
        for (int ni = 0; ni < 4; ni++) {
            int ow = wcol * 32 + ni * 8 + 2 * tq;
            if (ow < OHW) {
                y0[ow] = acc[mi][ni][0] + bias0;
                y1[ow] = acc[mi][ni][2] + bias1;
            }
            if (ow + 1 < OHW) {
                y0[ow + 1] = acc[mi][ni][1] + bias0;
                y1[ow + 1] = acc[mi][ni][3] + bias1;
            }
        }
    }
}

// ---------------------------------------------------------------------------
// Launch. Inputs: x, h, Wh, bh, Wb, bb. Output float32.
// ---------------------------------------------------------------------------
extern "C" void kernel_launch(void* const* d_in, const int* in_sizes, int n_in,
                              void* d_out, int out_size) {
    const float* x  = (const float*)d_in[0];
    const float* h  = (const float*)d_in[1];
    const float* Wh = (const float*)d_in[2];
    const float* bh = (const float*)d_in[3];
    const float* Wb = (const float*)d_in[4];
    const float* bb = (const float*)d_in[5];
    float* y = (float*)d_out;

    cudaFuncSetAttribute(conv_mma_kernel,
                         cudaFuncAttributeMaxDynamicSharedMemorySize, CONV_SMEM);

    hyper_gemm_kernel<<<288, 256, HD * 8 * 8>>>(Wh, h, bh);   // 32KB smem
    xpose_kernel<<<dim3(HW, B_SZ), 256>>>(x);
    hyper_bias_kernel<<<(B_SZ * COUT) / 8, 256>>>(h, Wb, bb);
    conv_mma_kernel<<<dim3(OHW, B_SZ), 256, CONV_SMEM>>>(y);
}